// round 4
// baseline (speedup 1.0000x reference)
#include <cuda_runtime.h>
#include <cuda_fp16.h>
#include <mma.h>

using namespace nvcuda::wmma;

// ---------------------------------------------------------------------------
// LSTMActorCritic: NSEQ=256, T=1024, OBS=128, ACT=16, H=64, N=262144
//
//  K0 prep_kernel   : one-time fp32->fp16 weight conversion into device
//                     globals; Whh additionally split into hi+lo fp16 planes.
//  K1 mlp_gx_kernel : tensor-core fused GEMM chain per 128-row tile:
//                     obs -> tanh -> tanh -> gx = feat@Wih.T (no bias),
//                     gates accumulators stored DIRECTLY to gmem.
//  K2 lstm_kernel   : 32 blocks x 16 seqs. Recurrent gates via wmma with
//                     split-fp16 (3 products: hi*hi + hi*lo + lo*hi) for
//                     fp32-class accuracy. Bias bih+bhh folded here.
//  K3 heads_kernel  : logits/log_softmax/logprob/entropy + value.
// ---------------------------------------------------------------------------

#define NSEQ   256
#define TLEN   1024
#define NROWS  262144      // NSEQ*TLEN
#define OBSD   128
#define HID    64
#define GATES  256         // 4*HID
#define ACT    16

// Scratch
__device__ float d_gx [2ull * NROWS * GATES];   // 536 MB, gx = feat@Wih.T (no bias)
__device__ float d_lat[2ull * NROWS * HID];     // 134 MB

// Pre-converted fp16 weights
__device__ __half g_w1h   [2][64 * OBSD];
__device__ __half g_w2h   [2][64 * 64];
__device__ __half g_wihh  [2][GATES * HID];
__device__ __half g_whh_hi[2][GATES * HID];
__device__ __half g_whh_lo[2][GATES * HID];

__device__ __forceinline__ float sigmoidf_(float x) {
    return __fdividef(1.f, 1.f + __expf(-x));
}
__device__ __forceinline__ float tanhf_(float x) {
    float e = __expf(-2.f * fabsf(x));
    float t = __fdividef(1.f - e, 1.f + e);
    return copysignf(t, x);
}

// ---------------------------------------------------------------------------
// K0: weight prep (runs every launch; deterministic; ~few us)
// ---------------------------------------------------------------------------
extern "C" __global__ void __launch_bounds__(256)
prep_kernel(const float* __restrict__ Wp1, const float* __restrict__ Wv1,
            const float* __restrict__ Wp2, const float* __restrict__ Wv2,
            const float* __restrict__ Wih_pi, const float* __restrict__ Wih_vf,
            const float* __restrict__ Whh_pi, const float* __restrict__ Whh_vf)
{
    const int tid = blockIdx.x * blockDim.x + threadIdx.x;
    const int nth = gridDim.x * blockDim.x;
    for (int i = tid; i < 64 * OBSD; i += nth) {
        g_w1h[0][i] = __float2half(Wp1[i]);
        g_w1h[1][i] = __float2half(Wv1[i]);
    }
    for (int i = tid; i < 64 * 64; i += nth) {
        g_w2h[0][i] = __float2half(Wp2[i]);
        g_w2h[1][i] = __float2half(Wv2[i]);
    }
    for (int i = tid; i < GATES * HID; i += nth) {
        g_wihh[0][i] = __float2half(Wih_pi[i]);
        g_wihh[1][i] = __float2half(Wih_vf[i]);
        float wp = Whh_pi[i];
        __half hp = __float2half(wp);
        g_whh_hi[0][i] = hp;
        g_whh_lo[0][i] = __float2half(wp - __half2float(hp));
        float wv = Whh_vf[i];
        __half hv = __float2half(wv);
        g_whh_hi[1][i] = hv;
        g_whh_lo[1][i] = __float2half(wv - __half2float(hv));
    }
}

// ---------------------------------------------------------------------------
// K1: tensor-core MLP + gate precompute. grid (2048,2), block 256 (8 warps).
// smem: s_x fp16 128x136 (aliased by s_f fp32 128x72), s_w1, s_w2, s_wih,
//       s_a fp16 128x72, b1/b2 fp32.
// ---------------------------------------------------------------------------
extern "C" __global__ void __launch_bounds__(256)
mlp_gx_kernel(const float* __restrict__ obs,
              const float* __restrict__ bp1, const float* __restrict__ bp2,
              const float* __restrict__ bv1, const float* __restrict__ bv2)
{
    extern __shared__ char smem[];
    __half* s_x   = (__half*)(smem);             // ld 136 (region 36864B)
    float*  s_f   = (float*)(smem);              // ld 72  (alias)
    __half* s_w1  = (__half*)(smem + 36864);     // 16384B
    __half* s_w2  = (__half*)(smem + 53248);     // 8192B
    __half* s_wih = (__half*)(smem + 61440);     // 32768B
    __half* s_a   = (__half*)(smem + 94208);     // 18432B
    float*  s_b1  = (float*)(smem + 112640);
    float*  s_b2  = s_b1 + 64;

    const int tid    = threadIdx.x;
    const int warp   = tid >> 5;
    const int branch = blockIdx.y;

    const float* b1 = branch ? bv1 : bp1;
    const float* b2 = branch ? bv2 : bp2;
    float* gx = d_gx + (size_t)branch * NROWS * GATES;

    // stage fp16 weights (vectorized copies)
    {
        const uint4* w1g  = (const uint4*)g_w1h[branch];
        const uint4* w2g  = (const uint4*)g_w2h[branch];
        const uint4* wihg = (const uint4*)g_wihh[branch];
        uint4* w1s  = (uint4*)s_w1;
        uint4* w2s  = (uint4*)s_w2;
        uint4* wihs = (uint4*)s_wih;
        #pragma unroll
        for (int i = 0; i < 4; i++)  w1s[tid + 256 * i]  = w1g[tid + 256 * i];    // 1024
        #pragma unroll
        for (int i = 0; i < 2; i++)  if (tid + 256 * i < 512) w2s[tid + 256 * i] = w2g[tid + 256 * i]; // 512
        #pragma unroll
        for (int i = 0; i < 8; i++)  wihs[tid + 256 * i] = wihg[tid + 256 * i];   // 2048
    }
    if (tid < 64)       s_b1[tid]      = b1[tid];
    else if (tid < 128) s_b2[tid - 64] = b2[tid - 64];

    // stage obs tile fp16
    const size_t row0 = (size_t)blockIdx.x * 128;
    for (int i = tid; i < 128 * 128; i += 256) {
        int r = i >> 7, k = i & 127;
        s_x[r * 136 + k] = __float2half(obs[(row0 + r) * OBSD + k]);
    }
    __syncthreads();

    fragment<matrix_a, 16, 16, 16, __half, row_major> fa;
    fragment<matrix_b, 16, 16, 16, __half, col_major> fb;
    fragment<accumulator, 16, 16, 16, float> fc[4];

    // ---- Layer 1: [128x128] @ [128x64] ----
    #pragma unroll
    for (int n = 0; n < 4; n++) fill_fragment(fc[n], 0.0f);
    #pragma unroll
    for (int k = 0; k < 8; k++) {
        load_matrix_sync(fa, s_x + warp * 16 * 136 + k * 16, 136);
        #pragma unroll
        for (int n = 0; n < 4; n++) {
            load_matrix_sync(fb, s_w1 + n * 16 * 128 + k * 16, 128);
            mma_sync(fc[n], fa, fb, fc[n]);
        }
    }
    __syncthreads();                       // all warps done reading s_x
    #pragma unroll
    for (int n = 0; n < 4; n++)
        store_matrix_sync(s_f + warp * 16 * 72 + n * 16, fc[n], 72, mem_row_major);
    __syncthreads();
    for (int i = tid; i < 128 * 64; i += 256) {
        int r = i >> 6, c = i & 63;
        s_a[r * 72 + c] = __float2half(tanhf_(s_f[r * 72 + c] + s_b1[c]));
    }
    __syncthreads();

    // ---- Layer 2: [128x64] @ [64x64] ----
    #pragma unroll
    for (int n = 0; n < 4; n++) fill_fragment(fc[n], 0.0f);
    #pragma unroll
    for (int k = 0; k < 4; k++) {
        load_matrix_sync(fa, s_a + warp * 16 * 72 + k * 16, 72);
        #pragma unroll
        for (int n = 0; n < 4; n++) {
            load_matrix_sync(fb, s_w2 + n * 16 * 64 + k * 16, 64);
            mma_sync(fc[n], fa, fb, fc[n]);
        }
    }
    #pragma unroll
    for (int n = 0; n < 4; n++)
        store_matrix_sync(s_f + warp * 16 * 72 + n * 16, fc[n], 72, mem_row_major);
    __syncthreads();
    for (int i = tid; i < 128 * 64; i += 256) {
        int r = i >> 6, c = i & 63;
        s_a[r * 72 + c] = __float2half(tanhf_(s_f[r * 72 + c] + s_b2[c]));
    }
    __syncthreads();

    // ---- Gates: [128x64] @ [64x256], accumulators straight to gmem ----
    float* gxw = gx + (row0 + warp * 16) * GATES;
    #pragma unroll 1
    for (int ch = 0; ch < 4; ch++) {
        #pragma unroll
        for (int n = 0; n < 4; n++) fill_fragment(fc[n], 0.0f);
        #pragma unroll
        for (int k = 0; k < 4; k++) {
            load_matrix_sync(fa, s_a + warp * 16 * 72 + k * 16, 72);
            #pragma unroll
            for (int n = 0; n < 4; n++) {
                load_matrix_sync(fb, s_wih + (ch * 64 + n * 16) * 64 + k * 16, 64);
                mma_sync(fc[n], fa, fb, fc[n]);
            }
        }
        #pragma unroll
        for (int n = 0; n < 4; n++)
            store_matrix_sync(gxw + ch * 64 + n * 16, fc[n], GATES, mem_row_major);
    }
}

// ---------------------------------------------------------------------------
// K2: tensor-core recurrent loop. 32 blocks (16 per lstm), 16 seqs each,
// 256 threads (8 warps; warp w owns gate chunk [32w, 32w+32)).
// Elementwise mapping: thread = (s = tid>>4, jbase = (tid&15)*4), 4 elems.
// smem layout (dynamic, 87104 B):
//   0      whh_hi  fp16 256x64        32768
//   32768  whh_lo  fp16 256x64        32768
//   65536  gacc    fp32 16 x ld264    16896
//   82432  h_hi    fp16 16 x ld72      2304
//   84736  h_lo    fp16 16 x ld72      2304
//   87040  ebuf    fp32 16               64
// ---------------------------------------------------------------------------
extern "C" __global__ void __launch_bounds__(256)
lstm_kernel(const float* __restrict__ eps,
            const float* __restrict__ h0_pi, const float* __restrict__ c0_pi,
            const float* __restrict__ h0_vf, const float* __restrict__ c0_vf,
            const float* __restrict__ bih_pi, const float* __restrict__ bhh_pi,
            const float* __restrict__ bih_vf, const float* __restrict__ bhh_vf)
{
    extern __shared__ char smem[];
    __half* s_whi = (__half*)(smem);
    __half* s_wlo = (__half*)(smem + 32768);
    float*  gacc  = (float*)(smem + 65536);      // ld 264
    __half* s_hhi = (__half*)(smem + 82432);     // ld 72
    __half* s_hlo = (__half*)(smem + 84736);     // ld 72
    float*  ebuf  = (float*)(smem + 87040);

    const int tid  = threadIdx.x;
    const int warp = tid >> 5;
    const int lstm = blockIdx.x >> 4;
    const int seg  = blockIdx.x & 15;
    const int seq0 = seg * 16;

    const float* h0  = lstm ? h0_vf  : h0_pi;
    const float* c0  = lstm ? c0_vf  : c0_pi;
    const float* bih = lstm ? bih_vf : bih_pi;
    const float* bhh = lstm ? bhh_vf : bhh_pi;
    const float* gx  = d_gx  + (size_t)lstm * NROWS * GATES;
    float*       lat = d_lat + (size_t)lstm * NROWS * HID;

    // stage split Whh
    {
        const uint4* hig = (const uint4*)g_whh_hi[lstm];
        const uint4* log_ = (const uint4*)g_whh_lo[lstm];
        uint4* his = (uint4*)s_whi;
        uint4* los = (uint4*)s_wlo;
        #pragma unroll
        for (int i = 0; i < 8; i++) {
            his[tid + 256 * i] = hig[tid + 256 * i];
            los[tid + 256 * i] = log_[tid + 256 * i];
        }
    }

    // elementwise identity
    const int s     = tid >> 4;
    const int jbase = (tid & 15) * 4;
    const int seq   = seq0 + s;

    // biases for this thread's 16 gate slots
    float4 bg[4];
    #pragma unroll
    for (int g = 0; g < 4; g++) {
        float4 a = *(const float4*)(bih + g * 64 + jbase);
        float4 b = *(const float4*)(bhh + g * 64 + jbase);
        bg[g] = make_float4(a.x + b.x, a.y + b.y, a.z + b.z, a.w + b.w);
    }

    // init h, c with episode mask at t=0
    float c[4];
    {
        float  e0 = eps[(size_t)seq * TLEN];
        float  m  = 1.f - e0;
        float4 hv = *(const float4*)(h0 + seq * HID + jbase);
        float4 cv = *(const float4*)(c0 + seq * HID + jbase);
        c[0] = cv.x * m; c[1] = cv.y * m; c[2] = cv.z * m; c[3] = cv.w * m;
        float hm[4] = {hv.x * m, hv.y * m, hv.z * m, hv.w * m};
        #pragma unroll
        for (int q = 0; q < 4; q++) {
            __half hi = __float2half(hm[q]);
            s_hhi[s * 72 + jbase + q] = hi;
            s_hlo[s * 72 + jbase + q] = __float2half(hm[q] - __half2float(hi));
        }
    }

    // gx prefetch buffers (t=0) and eps pipeline
    float4 gxb[2][4];
    #pragma unroll
    for (int g = 0; g < 4; g++)
        gxb[0][g] = *(const float4*)(gx + ((size_t)seq * TLEN) * GATES + g * 64 + jbase);
    float e1 = 0.f, e2 = 0.f;
    if (tid < 16) e1 = eps[(size_t)(seq0 + tid) * TLEN + 1];
    __syncthreads();

    fragment<matrix_a, 16, 16, 16, __half, row_major> fahi, falo;
    fragment<matrix_b, 16, 16, 16, __half, col_major> fbhi, fblo;
    fragment<accumulator, 16, 16, 16, float> fc[2];

    const int nb0 = warp * 32;   // this warp's gate chunk

    for (int t = 0; t < TLEN; t++) {
        const int cur = t & 1, nxt = cur ^ 1;

        if (tid < 16 && t + 2 < TLEN)
            e2 = eps[(size_t)(seq0 + tid) * TLEN + t + 2];

        // gates = h @ Whh.T (split fp16, 3 products)
        #pragma unroll
        for (int n = 0; n < 2; n++) fill_fragment(fc[n], 0.0f);
        #pragma unroll
        for (int k = 0; k < 4; k++) {
            load_matrix_sync(fahi, s_hhi + k * 16, 72);
            load_matrix_sync(falo, s_hlo + k * 16, 72);
            #pragma unroll
            for (int n = 0; n < 2; n++) {
                load_matrix_sync(fbhi, s_whi + (nb0 + n * 16) * 64 + k * 16, 64);
                load_matrix_sync(fblo, s_wlo + (nb0 + n * 16) * 64 + k * 16, 64);
                mma_sync(fc[n], fahi, fbhi, fc[n]);
                mma_sync(fc[n], fahi, fblo, fc[n]);
                mma_sync(fc[n], falo, fbhi, fc[n]);
            }
        }
        #pragma unroll
        for (int n = 0; n < 2; n++)
            store_matrix_sync(gacc + nb0 + n * 16, fc[n], 264, mem_row_major);

        // prefetch next step's gx
        if (t + 1 < TLEN) {
            #pragma unroll
            for (int g = 0; g < 4; g++)
                gxb[nxt][g] = *(const float4*)(gx + ((size_t)seq * TLEN + t + 1) * GATES + g * 64 + jbase);
        }
        if (tid < 16) ebuf[tid] = (t + 1 < TLEN) ? e1 : 0.f;
        __syncthreads();   // gacc + ebuf visible

        // elementwise: 4 elems per thread
        {
            float4 gi = *(const float4*)(gacc + s * 264 +       jbase);
            float4 gf = *(const float4*)(gacc + s * 264 +  64 + jbase);
            float4 gg = *(const float4*)(gacc + s * 264 + 128 + jbase);
            float4 go = *(const float4*)(gacc + s * 264 + 192 + jbase);
            float m = 1.f - ebuf[s];
            float hout[4];
            float iv[4] = {gi.x, gi.y, gi.z, gi.w};
            float fv[4] = {gf.x, gf.y, gf.z, gf.w};
            float gv[4] = {gg.x, gg.y, gg.z, gg.w};
            float ov[4] = {go.x, go.y, go.z, go.w};
            #pragma unroll
            for (int q = 0; q < 4; q++) {
                float gii = iv[q] + ((const float*)&gxb[cur][0])[q] + ((const float*)&bg[0])[q];
                float gff = fv[q] + ((const float*)&gxb[cur][1])[q] + ((const float*)&bg[1])[q];
                float ggg = gv[q] + ((const float*)&gxb[cur][2])[q] + ((const float*)&bg[2])[q];
                float goo = ov[q] + ((const float*)&gxb[cur][3])[q] + ((const float*)&bg[3])[q];
                c[q] = sigmoidf_(gff) * c[q] + sigmoidf_(gii) * tanhf_(ggg);
                float h = sigmoidf_(goo) * tanhf_(c[q]);
                hout[q] = h;
                c[q] *= m;
                float hm = h * m;
                __half hi = __float2half(hm);
                s_hhi[s * 72 + jbase + q] = hi;
                s_hlo[s * 72 + jbase + q] = __float2half(hm - __half2float(hi));
            }
            *(float4*)(lat + ((size_t)seq * TLEN + t) * HID + jbase) =
                make_float4(hout[0], hout[1], hout[2], hout[3]);
        }
        e1 = e2;
        __syncthreads();   // h tiles ready for next MMA
    }
}

// ---------------------------------------------------------------------------
// K3: heads. grid 2048 blocks, 128 threads, block handles 128 rows.
// ---------------------------------------------------------------------------
extern "C" __global__ void __launch_bounds__(128)
heads_kernel(const int* __restrict__ action,
             const float* __restrict__ Wa, const float* __restrict__ ba,
             const float* __restrict__ Wc, const float* __restrict__ bc,
             float* __restrict__ out)
{
    __shared__ float tile[64 * 129];
    __shared__ float was[ACT * HID];
    __shared__ float bas[ACT];
    __shared__ float wcs[HID];
    __shared__ float bcs;

    const int tid = threadIdx.x;
    const int r0  = blockIdx.x * 128;
    const float* lat_pi = d_lat;
    const float* lat_vf = d_lat + (size_t)NROWS * HID;

    for (int i = tid; i < ACT * HID; i += 128) was[i] = Wa[i];
    if (tid < ACT) bas[tid] = ba[tid];
    if (tid < HID) wcs[tid] = Wc[tid];
    if (tid == 0)  bcs = bc[0];

    for (int i = tid; i < 128 * HID; i += 128) {
        int r = i >> 6, k = i & 63;
        tile[k * 129 + r] = lat_pi[(size_t)r0 * HID + i];
    }
    __syncthreads();

    const int n = r0 + tid;
    float l[ACT];
    #pragma unroll
    for (int a = 0; a < ACT; a++) l[a] = bas[a];
    #pragma unroll 1
    for (int k = 0; k < HID; k++) {
        float x = tile[k * 129 + tid];
        #pragma unroll
        for (int a = 0; a < ACT; a++) l[a] = fmaf(was[a * HID + k], x, l[a]);
    }

    float m = l[0];
    #pragma unroll
    for (int a = 1; a < ACT; a++) m = fmaxf(m, l[a]);
    float se = 0.f;
    #pragma unroll
    for (int a = 0; a < ACT; a++) se += __expf(l[a] - m);
    float lse = m + __logf(se);
    float ent = 0.f;
    #pragma unroll
    for (int a = 0; a < ACT; a++) { float lp = l[a] - lse; ent += __expf(lp) * lp; }
    int   act   = action[n];
    float lpact = l[act] - lse;
    __syncthreads();

    for (int i = tid; i < 128 * HID; i += 128) {
        int r = i >> 6, k = i & 63;
        tile[k * 129 + r] = lat_vf[(size_t)r0 * HID + i];
    }
    __syncthreads();

    float v = bcs;
    #pragma unroll
    for (int k = 0; k < HID; k++) v = fmaf(wcs[k], tile[k * 129 + tid], v);

    out[n]             = lpact;
    out[NROWS + n]     = -ent;
    out[2 * NROWS + n] = v;
}

// ---------------------------------------------------------------------------
extern "C" void kernel_launch(void* const* d_in, const int* in_sizes, int n_in,
                              void* d_out, int out_size)
{
    const float* obs     = (const float*)d_in[0];
    const int*   action  = (const int*)  d_in[1];
    const float* eps     = (const float*)d_in[2];
    const float* h_pi    = (const float*)d_in[3];
    const float* c_pi    = (const float*)d_in[4];
    const float* h_vf    = (const float*)d_in[5];
    const float* c_vf    = (const float*)d_in[6];
    const float* Wp1     = (const float*)d_in[7];
    const float* bp1     = (const float*)d_in[8];
    const float* Wp2     = (const float*)d_in[9];
    const float* bp2     = (const float*)d_in[10];
    const float* Wv1     = (const float*)d_in[11];
    const float* bv1     = (const float*)d_in[12];
    const float* Wv2     = (const float*)d_in[13];
    const float* bv2     = (const float*)d_in[14];
    const float* Wih_pi  = (const float*)d_in[15];
    const float* Whh_pi  = (const float*)d_in[16];
    const float* bih_pi  = (const float*)d_in[17];
    const float* bhh_pi  = (const float*)d_in[18];
    const float* Wih_vf  = (const float*)d_in[19];
    const float* Whh_vf  = (const float*)d_in[20];
    const float* bih_vf  = (const float*)d_in[21];
    const float* bhh_vf  = (const float*)d_in[22];
    const float* Wa      = (const float*)d_in[23];
    const float* ba      = (const float*)d_in[24];
    const float* Wc      = (const float*)d_in[25];
    const float* bc      = (const float*)d_in[26];
    float* out = (float*)d_out;

    const int SMEM_MLP  = 114688;
    const int SMEM_LSTM = 87104;
    cudaFuncSetAttribute(mlp_gx_kernel, cudaFuncAttributeMaxDynamicSharedMemorySize, SMEM_MLP);
    cudaFuncSetAttribute(lstm_kernel,   cudaFuncAttributeMaxDynamicSharedMemorySize, SMEM_LSTM);

    prep_kernel<<<64, 256>>>(Wp1, Wv1, Wp2, Wv2, Wih_pi, Wih_vf, Whh_pi, Whh_vf);

    mlp_gx_kernel<<<dim3(2048, 2), 256, SMEM_MLP>>>(obs, bp1, bp2, bv1, bv2);

    lstm_kernel<<<32, 256, SMEM_LSTM>>>(eps, h_pi, c_pi, h_vf, c_vf,
                                        bih_pi, bhh_pi, bih_vf, bhh_vf);

    heads_kernel<<<2048, 128>>>(action, Wa, ba, Wc, bc, out);
}

// round 5
// speedup vs baseline: 3.3015x; 3.3015x over previous
#include <cuda_runtime.h>
#include <cuda_fp16.h>
#include <mma.h>

using namespace nvcuda::wmma;

// ---------------------------------------------------------------------------
// LSTMActorCritic: NSEQ=256, T=1024, OBS=128, ACT=16, H=64, N=262144
//
//  K0 prep_kernel   : one-time fp32->fp16 weight conversion (MLP weights).
//  K1 mlp_gx_kernel : tensor-core fused GEMM chain per 128-row tile:
//                     obs -> tanh -> tanh -> gx = feat@Wih.T (no bias),
//                     gate accumulators stored DIRECTLY to gmem.
//  K2 lstm_kernel   : fp32 weight-stationary recurrence (PROVEN R2 design):
//                     256 blocks x 2 seqs, thread=gate, f32x2 packed FMAs,
//                     h broadcast via smem, 2 barriers/step. bih+bhh folded
//                     here (gx is bias-free).
//  K3 heads_kernel  : logits/log_softmax/logprob/entropy + value.
// ---------------------------------------------------------------------------

typedef unsigned long long ull;

#define NSEQ   256
#define TLEN   1024
#define NROWS  262144      // NSEQ*TLEN
#define OBSD   128
#define HID    64
#define GATES  256         // 4*HID
#define ACT    16

// Scratch
__device__ float d_gx [2ull * NROWS * GATES];   // 536 MB, gx = feat@Wih.T (no bias)
__device__ float d_lat[2ull * NROWS * HID];     // 134 MB

// Pre-converted fp16 weights (MLP path only)
__device__ __half g_w1h [2][64 * OBSD];
__device__ __half g_w2h [2][64 * 64];
__device__ __half g_wihh[2][GATES * HID];

// ---------------- packed fp32x2 helpers ----------------
__device__ __forceinline__ ull pk2(float lo, float hi) {
    ull r; asm("mov.b64 %0,{%1,%2};" : "=l"(r) : "f"(lo), "f"(hi)); return r;
}
__device__ __forceinline__ float hsum2(ull v) {
    float a, b; asm("mov.b64 {%0,%1}, %2;" : "=f"(a), "=f"(b) : "l"(v)); return a + b;
}
__device__ __forceinline__ void fma2(ull &acc, ull a, ull b) {
    asm("fma.rn.f32x2 %0,%1,%2,%0;" : "+l"(acc) : "l"(a), "l"(b));
}

__device__ __forceinline__ float sigmoidf_(float x) {
    return __fdividef(1.f, 1.f + __expf(-x));
}
__device__ __forceinline__ float tanhf_(float x) {
    float e = __expf(-2.f * fabsf(x));
    float t = __fdividef(1.f - e, 1.f + e);
    return copysignf(t, x);
}

// ---------------------------------------------------------------------------
// K0: weight prep
// ---------------------------------------------------------------------------
extern "C" __global__ void __launch_bounds__(256)
prep_kernel(const float* __restrict__ Wp1, const float* __restrict__ Wv1,
            const float* __restrict__ Wp2, const float* __restrict__ Wv2,
            const float* __restrict__ Wih_pi, const float* __restrict__ Wih_vf)
{
    const int tid = blockIdx.x * blockDim.x + threadIdx.x;
    const int nth = gridDim.x * blockDim.x;
    for (int i = tid; i < 64 * OBSD; i += nth) {
        g_w1h[0][i] = __float2half(Wp1[i]);
        g_w1h[1][i] = __float2half(Wv1[i]);
    }
    for (int i = tid; i < 64 * 64; i += nth) {
        g_w2h[0][i] = __float2half(Wp2[i]);
        g_w2h[1][i] = __float2half(Wv2[i]);
    }
    for (int i = tid; i < GATES * HID; i += nth) {
        g_wihh[0][i] = __float2half(Wih_pi[i]);
        g_wihh[1][i] = __float2half(Wih_vf[i]);
    }
}

// ---------------------------------------------------------------------------
// K1: tensor-core MLP + gate precompute. grid (2048,2), block 256 (8 warps).
// ---------------------------------------------------------------------------
extern "C" __global__ void __launch_bounds__(256)
mlp_gx_kernel(const float* __restrict__ obs,
              const float* __restrict__ bp1, const float* __restrict__ bp2,
              const float* __restrict__ bv1, const float* __restrict__ bv2)
{
    extern __shared__ char smem[];
    __half* s_x   = (__half*)(smem);             // ld 136 (region 36864B)
    float*  s_f   = (float*)(smem);              // ld 72  (alias)
    __half* s_w1  = (__half*)(smem + 36864);     // 16384B
    __half* s_w2  = (__half*)(smem + 53248);     // 8192B
    __half* s_wih = (__half*)(smem + 61440);     // 32768B
    __half* s_a   = (__half*)(smem + 94208);     // 18432B
    float*  s_b1  = (float*)(smem + 112640);
    float*  s_b2  = s_b1 + 64;

    const int tid    = threadIdx.x;
    const int warp   = tid >> 5;
    const int branch = blockIdx.y;

    const float* b1 = branch ? bv1 : bp1;
    const float* b2 = branch ? bv2 : bp2;
    float* gx = d_gx + (size_t)branch * NROWS * GATES;

    // stage fp16 weights (vectorized copies)
    {
        const uint4* w1g  = (const uint4*)g_w1h[branch];
        const uint4* w2g  = (const uint4*)g_w2h[branch];
        const uint4* wihg = (const uint4*)g_wihh[branch];
        uint4* w1s  = (uint4*)s_w1;
        uint4* w2s  = (uint4*)s_w2;
        uint4* wihs = (uint4*)s_wih;
        #pragma unroll
        for (int i = 0; i < 4; i++)  w1s[tid + 256 * i]  = w1g[tid + 256 * i];
        #pragma unroll
        for (int i = 0; i < 2; i++)  if (tid + 256 * i < 512) w2s[tid + 256 * i] = w2g[tid + 256 * i];
        #pragma unroll
        for (int i = 0; i < 8; i++)  wihs[tid + 256 * i] = wihg[tid + 256 * i];
    }
    if (tid < 64)       s_b1[tid]      = b1[tid];
    else if (tid < 128) s_b2[tid - 64] = b2[tid - 64];

    // stage obs tile fp16
    const size_t row0 = (size_t)blockIdx.x * 128;
    for (int i = tid; i < 128 * 128; i += 256) {
        int r = i >> 7, k = i & 127;
        s_x[r * 136 + k] = __float2half(obs[(row0 + r) * OBSD + k]);
    }
    __syncthreads();

    fragment<matrix_a, 16, 16, 16, __half, row_major> fa;
    fragment<matrix_b, 16, 16, 16, __half, col_major> fb;
    fragment<accumulator, 16, 16, 16, float> fc[4];

    // ---- Layer 1: [128x128] @ [128x64] ----
    #pragma unroll
    for (int n = 0; n < 4; n++) fill_fragment(fc[n], 0.0f);
    #pragma unroll
    for (int k = 0; k < 8; k++) {
        load_matrix_sync(fa, s_x + warp * 16 * 136 + k * 16, 136);
        #pragma unroll
        for (int n = 0; n < 4; n++) {
            load_matrix_sync(fb, s_w1 + n * 16 * 128 + k * 16, 128);
            mma_sync(fc[n], fa, fb, fc[n]);
        }
    }
    __syncthreads();
    #pragma unroll
    for (int n = 0; n < 4; n++)
        store_matrix_sync(s_f + warp * 16 * 72 + n * 16, fc[n], 72, mem_row_major);
    __syncthreads();
    for (int i = tid; i < 128 * 64; i += 256) {
        int r = i >> 6, c = i & 63;
        s_a[r * 72 + c] = __float2half(tanhf_(s_f[r * 72 + c] + s_b1[c]));
    }
    __syncthreads();

    // ---- Layer 2: [128x64] @ [64x64] ----
    #pragma unroll
    for (int n = 0; n < 4; n++) fill_fragment(fc[n], 0.0f);
    #pragma unroll
    for (int k = 0; k < 4; k++) {
        load_matrix_sync(fa, s_a + warp * 16 * 72 + k * 16, 72);
        #pragma unroll
        for (int n = 0; n < 4; n++) {
            load_matrix_sync(fb, s_w2 + n * 16 * 64 + k * 16, 64);
            mma_sync(fc[n], fa, fb, fc[n]);
        }
    }
    #pragma unroll
    for (int n = 0; n < 4; n++)
        store_matrix_sync(s_f + warp * 16 * 72 + n * 16, fc[n], 72, mem_row_major);
    __syncthreads();
    for (int i = tid; i < 128 * 64; i += 256) {
        int r = i >> 6, c = i & 63;
        s_a[r * 72 + c] = __float2half(tanhf_(s_f[r * 72 + c] + s_b2[c]));
    }
    __syncthreads();

    // ---- Gates: [128x64] @ [64x256], accumulators straight to gmem ----
    float* gxw = gx + (row0 + warp * 16) * GATES;
    #pragma unroll 1
    for (int ch = 0; ch < 4; ch++) {
        #pragma unroll
        for (int n = 0; n < 4; n++) fill_fragment(fc[n], 0.0f);
        #pragma unroll
        for (int k = 0; k < 4; k++) {
            load_matrix_sync(fa, s_a + warp * 16 * 72 + k * 16, 72);
            #pragma unroll
            for (int n = 0; n < 4; n++) {
                load_matrix_sync(fb, s_wih + (ch * 64 + n * 16) * 64 + k * 16, 64);
                mma_sync(fc[n], fa, fb, fc[n]);
            }
        }
        #pragma unroll
        for (int n = 0; n < 4; n++)
            store_matrix_sync(gxw + ch * 64 + n * 16, fc[n], GATES, mem_row_major);
    }
}

// ---------------------------------------------------------------------------
// K2: recurrent loop (proven fp32 design). grid 256 blocks, 256 threads.
// Thread tid = gate tid for both of its block's 2 sequences; weights
// register-resident as f32x2 pairs; h broadcast from smem.
// gx is bias-free -> bg = bih[tid]+bhh[tid] added here.
// ---------------------------------------------------------------------------
extern "C" __global__ void __launch_bounds__(256, 2)
lstm_kernel(const float* __restrict__ Whh_pi, const float* __restrict__ Whh_vf,
            const float* __restrict__ eps,
            const float* __restrict__ h0_pi, const float* __restrict__ c0_pi,
            const float* __restrict__ h0_vf, const float* __restrict__ c0_vf,
            const float* __restrict__ bih_pi, const float* __restrict__ bhh_pi,
            const float* __restrict__ bih_vf, const float* __restrict__ bhh_vf)
{
    const int tid  = threadIdx.x;
    const int lstm = blockIdx.x >> 7;
    const int sp   = blockIdx.x & 127;
    const int seqA = sp * 2, seqB = sp * 2 + 1;

    const float* Whh = lstm ? Whh_vf : Whh_pi;
    const float* h0  = lstm ? h0_vf  : h0_pi;
    const float* c0  = lstm ? c0_vf  : c0_pi;
    const float* bih = lstm ? bih_vf : bih_pi;
    const float* bhh = lstm ? bhh_vf : bhh_pi;
    const float* gx  = d_gx  + (size_t)lstm * NROWS * GATES;
    float*       lat = d_lat + (size_t)lstm * NROWS * HID;

    __shared__ __align__(16) float hs[2][HID];
    __shared__ float gs[2][GATES];

    // Whh row tid -> 32 packed pairs in registers; bias folded per-gate
    ull wv[32];
    {
        const float4* wp = (const float4*)(Whh + tid * HID);
        #pragma unroll
        for (int i = 0; i < 16; i++) {
            float4 v = wp[i];
            wv[2*i]   = pk2(v.x, v.y);
            wv[2*i+1] = pk2(v.z, v.w);
        }
    }
    const float bg = bih[tid] + bhh[tid];

    const int s = tid >> 6, j = tid & 63;      // valid for tid < 128
    const int myseq = seqA + s;
    float c = 0.f, enext = 0.f;
    if (tid < 128) {
        float m = 1.f - eps[(size_t)myseq * TLEN];
        hs[s][j] = h0[myseq * HID + j] * m;
        c        = c0[myseq * HID + j] * m;
        enext    = eps[(size_t)myseq * TLEN + 1];
    }
    __syncthreads();

    float gA = gx[((size_t)seqA * TLEN) * GATES + tid];
    float gB = gx[((size_t)seqB * TLEN) * GATES + tid];

    const ulonglong2* hA2 = (const ulonglong2*)hs[0];
    const ulonglong2* hB2 = (const ulonglong2*)hs[1];

    for (int t = 0; t < TLEN; t++) {
        ull a0 = 0, a1 = 0, b0 = 0, b1_ = 0;
        #pragma unroll
        for (int kk = 0; kk < 16; kk++) {
            ulonglong2 ha = hA2[kk]; ulonglong2 hb = hB2[kk];
            fma2(a0,  wv[2*kk],   ha.x);  fma2(a1,  wv[2*kk+1], ha.y);
            fma2(b0,  wv[2*kk],   hb.x);  fma2(b1_, wv[2*kk+1], hb.y);
        }
        float gateA = gA + bg + hsum2(a0) + hsum2(a1);
        float gateB = gB + bg + hsum2(b0) + hsum2(b1_);

        // software-pipelined prefetch for step t+1 / mask for t+2
        if (t < TLEN - 1) {
            gA = gx[((size_t)seqA * TLEN + t + 1) * GATES + tid];
            gB = gx[((size_t)seqB * TLEN + t + 1) * GATES + tid];
        }
        float e2 = 0.f;
        if (tid < 128 && t < TLEN - 2) e2 = eps[(size_t)myseq * TLEN + t + 2];

        gs[0][tid] = gateA;
        gs[1][tid] = gateB;
        __syncthreads();

        if (tid < 128) {
            float gi = gs[s][j],       gf = gs[s][64 + j];
            float gg = gs[s][128 + j], go = gs[s][192 + j];
            c = sigmoidf_(gf) * c + sigmoidf_(gi) * tanhf_(gg);
            float h = sigmoidf_(go) * tanhf_(c);
            lat[((size_t)myseq * TLEN + t) * HID + j] = h;
            float m = 1.f - enext;    // mask for step t+1
            c *= m;
            hs[s][j] = h * m;
            enext = e2;
        }
        __syncthreads();
    }
}

// ---------------------------------------------------------------------------
// K3: heads. grid 2048 blocks, 128 threads, block handles 128 rows.
// ---------------------------------------------------------------------------
extern "C" __global__ void __launch_bounds__(128)
heads_kernel(const int* __restrict__ action,
             const float* __restrict__ Wa, const float* __restrict__ ba,
             const float* __restrict__ Wc, const float* __restrict__ bc,
             float* __restrict__ out)
{
    __shared__ float tile[64 * 129];
    __shared__ float was[ACT * HID];
    __shared__ float bas[ACT];
    __shared__ float wcs[HID];
    __shared__ float bcs;

    const int tid = threadIdx.x;
    const int r0  = blockIdx.x * 128;
    const float* lat_pi = d_lat;
    const float* lat_vf = d_lat + (size_t)NROWS * HID;

    for (int i = tid; i < ACT * HID; i += 128) was[i] = Wa[i];
    if (tid < ACT) bas[tid] = ba[tid];
    if (tid < HID) wcs[tid] = Wc[tid];
    if (tid == 0)  bcs = bc[0];

    for (int i = tid; i < 128 * HID; i += 128) {
        int r = i >> 6, k = i & 63;
        tile[k * 129 + r] = lat_pi[(size_t)r0 * HID + i];
    }
    __syncthreads();

    const int n = r0 + tid;
    float l[ACT];
    #pragma unroll
    for (int a = 0; a < ACT; a++) l[a] = bas[a];
    #pragma unroll 1
    for (int k = 0; k < HID; k++) {
        float x = tile[k * 129 + tid];
        #pragma unroll
        for (int a = 0; a < ACT; a++) l[a] = fmaf(was[a * HID + k], x, l[a]);
    }

    float m = l[0];
    #pragma unroll
    for (int a = 1; a < ACT; a++) m = fmaxf(m, l[a]);
    float se = 0.f;
    #pragma unroll
    for (int a = 0; a < ACT; a++) se += __expf(l[a] - m);
    float lse = m + __logf(se);
    float ent = 0.f;
    #pragma unroll
    for (int a = 0; a < ACT; a++) { float lp = l[a] - lse; ent += __expf(lp) * lp; }
    int   act   = action[n];
    float lpact = l[act] - lse;
    __syncthreads();

    for (int i = tid; i < 128 * HID; i += 128) {
        int r = i >> 6, k = i & 63;
        tile[k * 129 + r] = lat_vf[(size_t)r0 * HID + i];
    }
    __syncthreads();

    float v = bcs;
    #pragma unroll
    for (int k = 0; k < HID; k++) v = fmaf(wcs[k], tile[k * 129 + tid], v);

    out[n]             = lpact;
    out[NROWS + n]     = -ent;
    out[2 * NROWS + n] = v;
}

// ---------------------------------------------------------------------------
extern "C" void kernel_launch(void* const* d_in, const int* in_sizes, int n_in,
                              void* d_out, int out_size)
{
    const float* obs     = (const float*)d_in[0];
    const int*   action  = (const int*)  d_in[1];
    const float* eps     = (const float*)d_in[2];
    const float* h_pi    = (const float*)d_in[3];
    const float* c_pi    = (const float*)d_in[4];
    const float* h_vf    = (const float*)d_in[5];
    const float* c_vf    = (const float*)d_in[6];
    const float* Wp1     = (const float*)d_in[7];
    const float* bp1     = (const float*)d_in[8];
    const float* Wp2     = (const float*)d_in[9];
    const float* bp2     = (const float*)d_in[10];
    const float* Wv1     = (const float*)d_in[11];
    const float* bv1     = (const float*)d_in[12];
    const float* Wv2     = (const float*)d_in[13];
    const float* bv2     = (const float*)d_in[14];
    const float* Wih_pi  = (const float*)d_in[15];
    const float* Whh_pi  = (const float*)d_in[16];
    const float* bih_pi  = (const float*)d_in[17];
    const float* bhh_pi  = (const float*)d_in[18];
    const float* Wih_vf  = (const float*)d_in[19];
    const float* Whh_vf  = (const float*)d_in[20];
    const float* bih_vf  = (const float*)d_in[21];
    const float* bhh_vf  = (const float*)d_in[22];
    const float* Wa      = (const float*)d_in[23];
    const float* ba      = (const float*)d_in[24];
    const float* Wc      = (const float*)d_in[25];
    const float* bc      = (const float*)d_in[26];
    float* out = (float*)d_out;

    const int SMEM_MLP = 114688;
    cudaFuncSetAttribute(mlp_gx_kernel, cudaFuncAttributeMaxDynamicSharedMemorySize, SMEM_MLP);

    prep_kernel<<<64, 256>>>(Wp1, Wv1, Wp2, Wv2, Wih_pi, Wih_vf);

    mlp_gx_kernel<<<dim3(2048, 2), 256, SMEM_MLP>>>(obs, bp1, bp2, bv1, bv2);

    lstm_kernel<<<256, 256>>>(Whh_pi, Whh_vf, eps, h_pi, c_pi, h_vf, c_vf,
                              bih_pi, bhh_pi, bih_vf, bhh_vf);

    heads_kernel<<<2048, 128>>>(action, Wa, ba, Wc, bc, out);
}

// round 6
// speedup vs baseline: 3.4014x; 1.0302x over previous
#include <cuda_runtime.h>
#include <cuda_fp16.h>
#include <mma.h>

using namespace nvcuda::wmma;

// ---------------------------------------------------------------------------
// LSTMActorCritic: NSEQ=256, T=1024, OBS=128, ACT=16, H=64, N=262144
//
//  K0 prep_kernel   : one-time fp32->fp16 weight conversion (MLP weights).
//  K1 mlp_gx_kernel : tensor-core fused GEMM chain per 128-row tile:
//                     obs -> tanh -> tanh -> gx = feat@Wih.T (no bias),
//                     gate accumulators stored DIRECTLY to gmem.
//  K2 lstm_kernel   : fp32 weight-stationary recurrence, 256 blocks x 2 seqs,
//                     thread=gate, f32x2 packed FMAs, h broadcast via smem.
//                     NEW: 8-step register prefetch ring for gx (covers DRAM
//                     latency) + whole eps rows staged in smem.
//  K3 heads_kernel  : logits/log_softmax/logprob/entropy + value.
// ---------------------------------------------------------------------------

typedef unsigned long long ull;

#define NSEQ   256
#define TLEN   1024
#define NROWS  262144      // NSEQ*TLEN
#define OBSD   128
#define HID    64
#define GATES  256         // 4*HID
#define ACT    16
#define PF     8           // gx prefetch depth (steps)

// Scratch
__device__ float d_gx [2ull * NROWS * GATES];   // 536 MB, gx = feat@Wih.T (no bias)
__device__ float d_lat[2ull * NROWS * HID];     // 134 MB

// Pre-converted fp16 weights (MLP path only)
__device__ __half g_w1h [2][64 * OBSD];
__device__ __half g_w2h [2][64 * 64];
__device__ __half g_wihh[2][GATES * HID];

// ---------------- packed fp32x2 helpers ----------------
__device__ __forceinline__ ull pk2(float lo, float hi) {
    ull r; asm("mov.b64 %0,{%1,%2};" : "=l"(r) : "f"(lo), "f"(hi)); return r;
}
__device__ __forceinline__ float hsum2(ull v) {
    float a, b; asm("mov.b64 {%0,%1}, %2;" : "=f"(a), "=f"(b) : "l"(v)); return a + b;
}
__device__ __forceinline__ void fma2(ull &acc, ull a, ull b) {
    asm("fma.rn.f32x2 %0,%1,%2,%0;" : "+l"(acc) : "l"(a), "l"(b));
}

__device__ __forceinline__ float sigmoidf_(float x) {
    return __fdividef(1.f, 1.f + __expf(-x));
}
__device__ __forceinline__ float tanhf_(float x) {
    float e = __expf(-2.f * fabsf(x));
    float t = __fdividef(1.f - e, 1.f + e);
    return copysignf(t, x);
}

// ---------------------------------------------------------------------------
// K0: weight prep
// ---------------------------------------------------------------------------
extern "C" __global__ void __launch_bounds__(256)
prep_kernel(const float* __restrict__ Wp1, const float* __restrict__ Wv1,
            const float* __restrict__ Wp2, const float* __restrict__ Wv2,
            const float* __restrict__ Wih_pi, const float* __restrict__ Wih_vf)
{
    const int tid = blockIdx.x * blockDim.x + threadIdx.x;
    const int nth = gridDim.x * blockDim.x;
    for (int i = tid; i < 64 * OBSD; i += nth) {
        g_w1h[0][i] = __float2half(Wp1[i]);
        g_w1h[1][i] = __float2half(Wv1[i]);
    }
    for (int i = tid; i < 64 * 64; i += nth) {
        g_w2h[0][i] = __float2half(Wp2[i]);
        g_w2h[1][i] = __float2half(Wv2[i]);
    }
    for (int i = tid; i < GATES * HID; i += nth) {
        g_wihh[0][i] = __float2half(Wih_pi[i]);
        g_wihh[1][i] = __float2half(Wih_vf[i]);
    }
}

// ---------------------------------------------------------------------------
// K1: tensor-core MLP + gate precompute. grid (2048,2), block 256 (8 warps).
// ---------------------------------------------------------------------------
extern "C" __global__ void __launch_bounds__(256)
mlp_gx_kernel(const float* __restrict__ obs,
              const float* __restrict__ bp1, const float* __restrict__ bp2,
              const float* __restrict__ bv1, const float* __restrict__ bv2)
{
    extern __shared__ char smem[];
    __half* s_x   = (__half*)(smem);             // ld 136 (region 36864B)
    float*  s_f   = (float*)(smem);              // ld 72  (alias)
    __half* s_w1  = (__half*)(smem + 36864);     // 16384B
    __half* s_w2  = (__half*)(smem + 53248);     // 8192B
    __half* s_wih = (__half*)(smem + 61440);     // 32768B
    __half* s_a   = (__half*)(smem + 94208);     // 18432B
    float*  s_b1  = (float*)(smem + 112640);
    float*  s_b2  = s_b1 + 64;

    const int tid    = threadIdx.x;
    const int warp   = tid >> 5;
    const int branch = blockIdx.y;

    const float* b1 = branch ? bv1 : bp1;
    const float* b2 = branch ? bv2 : bp2;
    float* gx = d_gx + (size_t)branch * NROWS * GATES;

    // stage fp16 weights (vectorized copies)
    {
        const uint4* w1g  = (const uint4*)g_w1h[branch];
        const uint4* w2g  = (const uint4*)g_w2h[branch];
        const uint4* wihg = (const uint4*)g_wihh[branch];
        uint4* w1s  = (uint4*)s_w1;
        uint4* w2s  = (uint4*)s_w2;
        uint4* wihs = (uint4*)s_wih;
        #pragma unroll
        for (int i = 0; i < 4; i++)  w1s[tid + 256 * i]  = w1g[tid + 256 * i];
        #pragma unroll
        for (int i = 0; i < 2; i++)  if (tid + 256 * i < 512) w2s[tid + 256 * i] = w2g[tid + 256 * i];
        #pragma unroll
        for (int i = 0; i < 8; i++)  wihs[tid + 256 * i] = wihg[tid + 256 * i];
    }
    if (tid < 64)       s_b1[tid]      = b1[tid];
    else if (tid < 128) s_b2[tid - 64] = b2[tid - 64];

    // stage obs tile fp16
    const size_t row0 = (size_t)blockIdx.x * 128;
    for (int i = tid; i < 128 * 128; i += 256) {
        int r = i >> 7, k = i & 127;
        s_x[r * 136 + k] = __float2half(obs[(row0 + r) * OBSD + k]);
    }
    __syncthreads();

    fragment<matrix_a, 16, 16, 16, __half, row_major> fa;
    fragment<matrix_b, 16, 16, 16, __half, col_major> fb;
    fragment<accumulator, 16, 16, 16, float> fc[4];

    // ---- Layer 1: [128x128] @ [128x64] ----
    #pragma unroll
    for (int n = 0; n < 4; n++) fill_fragment(fc[n], 0.0f);
    #pragma unroll
    for (int k = 0; k < 8; k++) {
        load_matrix_sync(fa, s_x + warp * 16 * 136 + k * 16, 136);
        #pragma unroll
        for (int n = 0; n < 4; n++) {
            load_matrix_sync(fb, s_w1 + n * 16 * 128 + k * 16, 128);
            mma_sync(fc[n], fa, fb, fc[n]);
        }
    }
    __syncthreads();
    #pragma unroll
    for (int n = 0; n < 4; n++)
        store_matrix_sync(s_f + warp * 16 * 72 + n * 16, fc[n], 72, mem_row_major);
    __syncthreads();
    for (int i = tid; i < 128 * 64; i += 256) {
        int r = i >> 6, c = i & 63;
        s_a[r * 72 + c] = __float2half(tanhf_(s_f[r * 72 + c] + s_b1[c]));
    }
    __syncthreads();

    // ---- Layer 2: [128x64] @ [64x64] ----
    #pragma unroll
    for (int n = 0; n < 4; n++) fill_fragment(fc[n], 0.0f);
    #pragma unroll
    for (int k = 0; k < 4; k++) {
        load_matrix_sync(fa, s_a + warp * 16 * 72 + k * 16, 72);
        #pragma unroll
        for (int n = 0; n < 4; n++) {
            load_matrix_sync(fb, s_w2 + n * 16 * 64 + k * 16, 64);
            mma_sync(fc[n], fa, fb, fc[n]);
        }
    }
    #pragma unroll
    for (int n = 0; n < 4; n++)
        store_matrix_sync(s_f + warp * 16 * 72 + n * 16, fc[n], 72, mem_row_major);
    __syncthreads();
    for (int i = tid; i < 128 * 64; i += 256) {
        int r = i >> 6, c = i & 63;
        s_a[r * 72 + c] = __float2half(tanhf_(s_f[r * 72 + c] + s_b2[c]));
    }
    __syncthreads();

    // ---- Gates: [128x64] @ [64x256], accumulators straight to gmem ----
    float* gxw = gx + (row0 + warp * 16) * GATES;
    #pragma unroll 1
    for (int ch = 0; ch < 4; ch++) {
        #pragma unroll
        for (int n = 0; n < 4; n++) fill_fragment(fc[n], 0.0f);
        #pragma unroll
        for (int k = 0; k < 4; k++) {
            load_matrix_sync(fa, s_a + warp * 16 * 72 + k * 16, 72);
            #pragma unroll
            for (int n = 0; n < 4; n++) {
                load_matrix_sync(fb, s_wih + (ch * 64 + n * 16) * 64 + k * 16, 64);
                mma_sync(fc[n], fa, fb, fc[n]);
            }
        }
        #pragma unroll
        for (int n = 0; n < 4; n++)
            store_matrix_sync(gxw + ch * 64 + n * 16, fc[n], GATES, mem_row_major);
    }
}

// ---------------------------------------------------------------------------
// K2: recurrent loop. grid 256 blocks, 256 threads, 2 seqs/block.
// gx prefetched PF=8 steps ahead in a register ring (loop unrolled x8);
// eps rows staged in smem once.
// ---------------------------------------------------------------------------
extern "C" __global__ void __launch_bounds__(256, 2)
lstm_kernel(const float* __restrict__ Whh_pi, const float* __restrict__ Whh_vf,
            const float* __restrict__ eps,
            const float* __restrict__ h0_pi, const float* __restrict__ c0_pi,
            const float* __restrict__ h0_vf, const float* __restrict__ c0_vf,
            const float* __restrict__ bih_pi, const float* __restrict__ bhh_pi,
            const float* __restrict__ bih_vf, const float* __restrict__ bhh_vf)
{
    const int tid  = threadIdx.x;
    const int lstm = blockIdx.x >> 7;
    const int sp   = blockIdx.x & 127;
    const int seqA = sp * 2, seqB = sp * 2 + 1;

    const float* Whh = lstm ? Whh_vf : Whh_pi;
    const float* h0  = lstm ? h0_vf  : h0_pi;
    const float* c0  = lstm ? c0_vf  : c0_pi;
    const float* bih = lstm ? bih_vf : bih_pi;
    const float* bhh = lstm ? bhh_vf : bhh_pi;
    const float* gx  = d_gx  + (size_t)lstm * NROWS * GATES;
    float*       lat = d_lat + (size_t)lstm * NROWS * HID;

    __shared__ __align__(16) float hs[2][HID];
    __shared__ float gs[2][GATES];
    __shared__ float seps[2][TLEN];

    // stage episode-start rows for both sequences (coalesced)
    {
        const float4* eA = (const float4*)(eps + (size_t)seqA * TLEN);
        float4* sA = (float4*)seps[0];
        #pragma unroll
        for (int i = 0; i < 2; i++) sA[tid + 256 * i] = eA[tid + 256 * i];   // covers 2x1024 floats
    }

    // Whh row tid -> 32 packed pairs in registers; bias folded per-gate
    ull wv[32];
    {
        const float4* wp = (const float4*)(Whh + tid * HID);
        #pragma unroll
        for (int i = 0; i < 16; i++) {
            float4 v = wp[i];
            wv[2*i]   = pk2(v.x, v.y);
            wv[2*i+1] = pk2(v.z, v.w);
        }
    }
    const float bg = bih[tid] + bhh[tid];

    // gx prefetch ring: slots 0..PF-1 hold steps t..t+PF-1
    float gAb[PF], gBb[PF];
    const float* gxA = gx + (size_t)seqA * TLEN * GATES + tid;
    const float* gxB = gx + (size_t)seqB * TLEN * GATES + tid;
    #pragma unroll
    for (int p = 0; p < PF; p++) {
        gAb[p] = __ldg(gxA + (size_t)p * GATES);
        gBb[p] = __ldg(gxB + (size_t)p * GATES);
    }

    const int s = tid >> 6, j = tid & 63;      // valid for tid < 128
    const int myseq = seqA + s;
    float c = 0.f;
    __syncthreads();                           // seps staged
    if (tid < 128) {
        float m = 1.f - seps[s][0];
        hs[s][j] = h0[myseq * HID + j] * m;
        c        = c0[myseq * HID + j] * m;
    }
    __syncthreads();

    const ulonglong2* hA2 = (const ulonglong2*)hs[0];
    const ulonglong2* hB2 = (const ulonglong2*)hs[1];

    for (int tb = 0; tb < TLEN; tb += PF) {
        #pragma unroll
        for (int u = 0; u < PF; u++) {
            const int t = tb + u;

            ull a0 = 0, a1 = 0, b0 = 0, b1_ = 0;
            #pragma unroll
            for (int kk = 0; kk < 16; kk++) {
                ulonglong2 ha = hA2[kk]; ulonglong2 hb = hB2[kk];
                fma2(a0,  wv[2*kk],   ha.x);  fma2(a1,  wv[2*kk+1], ha.y);
                fma2(b0,  wv[2*kk],   hb.x);  fma2(b1_, wv[2*kk+1], hb.y);
            }
            float gateA = gAb[u] + bg + hsum2(a0) + hsum2(a1);
            float gateB = gBb[u] + bg + hsum2(b0) + hsum2(b1_);

            // refill ring slot u with step t+PF (8 steps ahead)
            if (t + PF < TLEN) {
                gAb[u] = __ldg(gxA + (size_t)(t + PF) * GATES);
                gBb[u] = __ldg(gxB + (size_t)(t + PF) * GATES);
            }

            gs[0][tid] = gateA;
            gs[1][tid] = gateB;
            __syncthreads();

            if (tid < 128) {
                float gi = gs[s][j],       gf = gs[s][64 + j];
                float gg = gs[s][128 + j], go = gs[s][192 + j];
                c = sigmoidf_(gf) * c + sigmoidf_(gi) * tanhf_(gg);
                float h = sigmoidf_(go) * tanhf_(c);
                lat[((size_t)myseq * TLEN + t) * HID + j] = h;
                // mask for step t+1 (garbage at t=1023 is never read)
                float m = 1.f - seps[s][(t + 1) & (TLEN - 1)];
                c *= m;
                hs[s][j] = h * m;
            }
            __syncthreads();
        }
    }
}

// ---------------------------------------------------------------------------
// K3: heads. grid 2048 blocks, 128 threads, block handles 128 rows.
// ---------------------------------------------------------------------------
extern "C" __global__ void __launch_bounds__(128)
heads_kernel(const int* __restrict__ action,
             const float* __restrict__ Wa, const float* __restrict__ ba,
             const float* __restrict__ Wc, const float* __restrict__ bc,
             float* __restrict__ out)
{
    __shared__ float tile[64 * 129];
    __shared__ float was[ACT * HID];
    __shared__ float bas[ACT];
    __shared__ float wcs[HID];
    __shared__ float bcs;

    const int tid = threadIdx.x;
    const int r0  = blockIdx.x * 128;
    const float* lat_pi = d_lat;
    const float* lat_vf = d_lat + (size_t)NROWS * HID;

    for (int i = tid; i < ACT * HID; i += 128) was[i] = Wa[i];
    if (tid < ACT) bas[tid] = ba[tid];
    if (tid < HID) wcs[tid] = Wc[tid];
    if (tid == 0)  bcs = bc[0];

    for (int i = tid; i < 128 * HID; i += 128) {
        int r = i >> 6, k = i & 63;
        tile[k * 129 + r] = lat_pi[(size_t)r0 * HID + i];
    }
    __syncthreads();

    const int n = r0 + tid;
    float l[ACT];
    #pragma unroll
    for (int a = 0; a < ACT; a++) l[a] = bas[a];
    #pragma unroll 1
    for (int k = 0; k < HID; k++) {
        float x = tile[k * 129 + tid];
        #pragma unroll
        for (int a = 0; a < ACT; a++) l[a] = fmaf(was[a * HID + k], x, l[a]);
    }

    float m = l[0];
    #pragma unroll
    for (int a = 1; a < ACT; a++) m = fmaxf(m, l[a]);
    float se = 0.f;
    #pragma unroll
    for (int a = 0; a < ACT; a++) se += __expf(l[a] - m);
    float lse = m + __logf(se);
    float ent = 0.f;
    #pragma unroll
    for (int a = 0; a < ACT; a++) { float lp = l[a] - lse; ent += __expf(lp) * lp; }
    int   act   = action[n];
    float lpact = l[act] - lse;
    __syncthreads();

    for (int i = tid; i < 128 * HID; i += 128) {
        int r = i >> 6, k = i & 63;
        tile[k * 129 + r] = lat_vf[(size_t)r0 * HID + i];
    }
    __syncthreads();

    float v = bcs;
    #pragma unroll
    for (int k = 0; k < HID; k++) v = fmaf(wcs[k], tile[k * 129 + tid], v);

    out[n]             = lpact;
    out[NROWS + n]     = -ent;
    out[2 * NROWS + n] = v;
}

// ---------------------------------------------------------------------------
extern "C" void kernel_launch(void* const* d_in, const int* in_sizes, int n_in,
                              void* d_out, int out_size)
{
    const float* obs     = (const float*)d_in[0];
    const int*   action  = (const int*)  d_in[1];
    const float* eps     = (const float*)d_in[2];
    const float* h_pi    = (const float*)d_in[3];
    const float* c_pi    = (const float*)d_in[4];
    const float* h_vf    = (const float*)d_in[5];
    const float* c_vf    = (const float*)d_in[6];
    const float* Wp1     = (const float*)d_in[7];
    const float* bp1     = (const float*)d_in[8];
    const float* Wp2     = (const float*)d_in[9];
    const float* bp2     = (const float*)d_in[10];
    const float* Wv1     = (const float*)d_in[11];
    const float* bv1     = (const float*)d_in[12];
    const float* Wv2     = (const float*)d_in[13];
    const float* bv2     = (const float*)d_in[14];
    const float* Wih_pi  = (const float*)d_in[15];
    const float* Whh_pi  = (const float*)d_in[16];
    const float* bih_pi  = (const float*)d_in[17];
    const float* bhh_pi  = (const float*)d_in[18];
    const float* Wih_vf  = (const float*)d_in[19];
    const float* Whh_vf  = (const float*)d_in[20];
    const float* bih_vf  = (const float*)d_in[21];
    const float* bhh_vf  = (const float*)d_in[22];
    const float* Wa      = (const float*)d_in[23];
    const float* ba      = (const float*)d_in[24];
    const float* Wc      = (const float*)d_in[25];
    const float* bc      = (const float*)d_in[26];
    float* out = (float*)d_out;

    const int SMEM_MLP = 114688;
    cudaFuncSetAttribute(mlp_gx_kernel, cudaFuncAttributeMaxDynamicSharedMemorySize, SMEM_MLP);

    prep_kernel<<<64, 256>>>(Wp1, Wv1, Wp2, Wv2, Wih_pi, Wih_vf);

    mlp_gx_kernel<<<dim3(2048, 2), 256, SMEM_MLP>>>(obs, bp1, bp2, bv1, bv2);

    lstm_kernel<<<256, 256>>>(Whh_pi, Whh_vf, eps, h_pi, c_pi, h_vf, c_vf,
                              bih_pi, bhh_pi, bih_vf, bhh_vf);

    heads_kernel<<<2048, 128>>>(action, Wa, ba, Wc, bc, out);
}